// round 11
// baseline (speedup 1.0000x reference)
#include <cuda_runtime.h>
#include <cuda_fp16.h>
#include <stdint.h>
#include <math.h>

#define NN 20000
#define EE 320000
#define E2 (2*EE)
#define HH 64

// ---------------- static scratch (no allocations allowed) ----------------
__device__ int   g_cnt[NN];
__device__ int   g_ptr[NN + 1];
__device__ int   g_rank[E2];
__device__ int   g_src[E2];
__device__ float g_ea5[E2 * 5];
__device__ float g_deg[NN];
__device__ float g_dis[NN];
__device__ float g_buf[5][NN * HH];

// ---------------- setup kernels ----------------

__global__ void k_zero_counts()
{
    int i = blockIdx.x * blockDim.x + threadIdx.x;
    if (i < NN) g_cnt[i] = 0;
}

__global__ void k_count(const int* __restrict__ ei)
{
    int j = blockIdx.x * blockDim.x + threadIdx.x;
    if (j >= EE) return;
    int a = ei[j], b = ei[EE + j];
    int r0 = atomicAdd(&g_cnt[b], 1);
    int r1 = atomicAdd(&g_cnt[a], 1);
    g_rank[j]      = r0;
    g_rank[EE + j] = r1;
}

__global__ void k_scan()
{
    __shared__ int sw[32];
    __shared__ int sTotal;
    __shared__ int sCarry;
    int t = threadIdx.x;
    int lane = t & 31, w = t >> 5;
    if (t == 0) sCarry = 0;
    for (int base = 0; base < NN; base += 1024) {
        __syncthreads();
        int carry = sCarry;
        int i = base + t;
        int v = (i < NN) ? g_cnt[i] : 0;
        int x = v;
        #pragma unroll
        for (int d = 1; d < 32; d <<= 1) {
            int y = __shfl_up_sync(0xffffffffu, x, d);
            if (lane >= d) x += y;
        }
        if (lane == 31) sw[w] = x;
        __syncthreads();
        if (w == 0) {
            int y = sw[lane];
            #pragma unroll
            for (int d = 1; d < 32; d <<= 1) {
                int z = __shfl_up_sync(0xffffffffu, y, d);
                if (lane >= d) y += z;
            }
            sw[lane] = y;
            if (lane == 31) sTotal = y;
        }
        __syncthreads();
        int incl = x + ((w > 0) ? sw[w - 1] : 0);
        if (i < NN) {
            g_ptr[i] = carry + incl - v;
            float df = (float)v;
            g_deg[i] = df;
            g_dis[i] = (v > 0) ? rsqrtf(df) : 0.f;
        }
        __syncthreads();
        if (t == 0) sCarry = carry + sTotal;
    }
    __syncthreads();
    if (t == 0) g_ptr[NN] = sCarry;
}

__global__ void k_scatter(const int* __restrict__ ei, const float* __restrict__ eattr)
{
    int j = blockIdx.x * blockDim.x + threadIdx.x;
    if (j >= EE) return;
    int a = ei[j], b = ei[EE + j];
    float e0 = eattr[j * 5 + 0];
    float e1 = eattr[j * 5 + 1];
    float e2 = eattr[j * 5 + 2];
    float e3 = eattr[j * 5 + 3];
    float e4 = eattr[j * 5 + 4];
    int p0 = g_ptr[b] + g_rank[j];
    int p1 = g_ptr[a] + g_rank[EE + j];
    g_src[p0] = a;
    g_src[p1] = b;
    float* q0 = g_ea5 + (size_t)p0 * 5;
    q0[0] = e0; q0[1] = e1; q0[2] = e2; q0[3] = e3; q0[4] = e4;
    float* q1 = g_ea5 + (size_t)p1 * 5;
    q1[0] = e0; q1[1] = e1; q1[2] = e2; q1[3] = e3; q1[4] = e4;
}

// ---------------- layer kernels ----------------

// first layer pre: XDb = x@W1[0:6]+b1, XS = x@W1[6:12]  (x = data_x[:,4:10])
__global__ void k_pre0(const float* __restrict__ data_x,
                       const float* __restrict__ W1, const float* __restrict__ b1,
                       float* __restrict__ XDb, float* __restrict__ XS)
{
    __shared__ float sW[12 * 64];
    int tid = threadIdx.x;
    for (int i = tid; i < 12 * 64; i += 256) sW[i] = W1[i];
    __syncthreads();
    int gid = blockIdx.x * 256 + tid;
    int v = gid >> 7;
    int j = gid & 127;
    if (v >= NN) return;
    const float* xr = data_x + v * 16 + 4;
    float x0 = xr[0], x1 = xr[1], x2 = xr[2], x3 = xr[3], x4 = xr[4], x5 = xr[5];
    if (j < 64) {
        float acc = b1[j];
        acc += x0 * sW[0 * 64 + j]; acc += x1 * sW[1 * 64 + j];
        acc += x2 * sW[2 * 64 + j]; acc += x3 * sW[3 * 64 + j];
        acc += x4 * sW[4 * 64 + j]; acc += x5 * sW[5 * 64 + j];
        XDb[v * 64 + j] = acc;
    } else {
        int c = j - 64;
        float acc = 0.f;
        acc += x0 * sW[6 * 64 + c];  acc += x1 * sW[7 * 64 + c];
        acc += x2 * sW[8 * 64 + c];  acc += x3 * sW[9 * 64 + c];
        acc += x4 * sW[10 * 64 + c]; acc += x5 * sW[11 * 64 + c];
        XS[v * 64 + c] = acc;
    }
}

// dual GEMM: out0 = A@Wa + ba, out1 = A@Wb  (A tile loaded once) — R8 version
__global__ void __launch_bounds__(256)
k_gemm64_dual(const float* __restrict__ A, const float* __restrict__ Wa,
              const float* __restrict__ ba, const float* __restrict__ Wb,
              float* __restrict__ out0, float* __restrict__ out1, int n)
{
    __shared__ float sW[64 * 64];
    __shared__ float sA[64 * 68];
    const int tid = threadIdx.x;
    const int rowBase = blockIdx.x * 64;
    const int c0 = (tid & 15) * 4;
    const int r0 = (tid >> 4) * 4;
    const int lr = tid >> 4;
    const int lc = (tid & 15) * 4;

    #pragma unroll
    for (int i = 0; i < 4; ++i) {
        int r = lr + i * 16;
        int gr = rowBase + r;
        float4 v = make_float4(0.f, 0.f, 0.f, 0.f);
        if (gr < n) v = *(const float4*)(A + (size_t)gr * 64 + lc);
        *(float4*)(&sA[r * 68 + lc]) = v;
    }

    #pragma unroll
    for (int half = 0; half < 2; ++half) {
        const float4* Wv = (const float4*)(half ? Wb : Wa);
        #pragma unroll
        for (int i = 0; i < 4; ++i)
            ((float4*)sW)[tid + i * 256] = Wv[tid + i * 256];
        __syncthreads();
        float acc[4][4] = {};
        #pragma unroll
        for (int k = 0; k < 64; ++k) {
            float4 b = *(const float4*)(&sW[k * 64 + c0]);
            float a0 = sA[(r0 + 0) * 68 + k];
            float a1 = sA[(r0 + 1) * 68 + k];
            float a2 = sA[(r0 + 2) * 68 + k];
            float a3 = sA[(r0 + 3) * 68 + k];
            acc[0][0] += a0 * b.x; acc[0][1] += a0 * b.y; acc[0][2] += a0 * b.z; acc[0][3] += a0 * b.w;
            acc[1][0] += a1 * b.x; acc[1][1] += a1 * b.y; acc[1][2] += a1 * b.z; acc[1][3] += a1 * b.w;
            acc[2][0] += a2 * b.x; acc[2][1] += a2 * b.y; acc[2][2] += a2 * b.z; acc[2][3] += a2 * b.w;
            acc[3][0] += a3 * b.x; acc[3][1] += a3 * b.y; acc[3][2] += a3 * b.z; acc[3][3] += a3 * b.w;
        }
        float4 bv = make_float4(0.f, 0.f, 0.f, 0.f);
        if (half == 0 && ba) bv = *(const float4*)(ba + c0);
        float* outp = half ? out1 : out0;
        #pragma unroll
        for (int i = 0; i < 4; ++i) {
            int gr = rowBase + r0 + i;
            if (gr < n) {
                float4 o;
                o.x = acc[i][0] + bv.x; o.y = acc[i][1] + bv.y;
                o.z = acc[i][2] + bv.z; o.w = acc[i][3] + bv.w;
                *(float4*)(outp + (size_t)gr * 64 + c0) = o;
            }
        }
        __syncthreads();
    }
}

// edge aggregation + fused GEMV epilogue:
//   agg[v] = sum_e relu( XDb[v] + XS[src_e] + ea_e@W1e )
//   out[v][c] = relu( agg[v]@W2[:,c] + deg[v]*b2[c] )
// half-warp per edge (as R8), then per-warp GEMV via smem-broadcast row.
__global__ void __launch_bounds__(256)
k_edge_gemv(const float* __restrict__ XDb, const float* __restrict__ XS,
            const float* __restrict__ W1e, const float* __restrict__ W2,
            const float* __restrict__ b2, float* __restrict__ out)
{
    __shared__ float sE[5 * 64];
    __shared__ float sW2[64 * 64];
    __shared__ float sRow[8][64];
    int tid = threadIdx.x;
    for (int i = tid; i < 5 * 64; i += 256) sE[i] = W1e[i];
    {
        const float4* Wv = (const float4*)W2;
        #pragma unroll
        for (int i = 0; i < 4; ++i)
            ((float4*)sW2)[tid + i * 256] = Wv[tid + i * 256];
    }
    __syncthreads();
    int wid = (blockIdx.x * 256 + tid) >> 5;
    int lane = tid & 31;
    int w = (tid >> 5);
    if (wid >= NN) return;
    int half = lane >> 4;
    int hl = lane & 15;
    int c0 = hl * 4;
    float4 xd = *(const float4*)(XDb + (size_t)wid * 64 + c0);
    float4 we[5];
    #pragma unroll
    for (int k = 0; k < 5; ++k) we[k] = *(const float4*)(sE + k * 64 + c0);
    int e0 = g_ptr[wid], e1 = g_ptr[wid + 1];
    float4 acc = make_float4(0.f, 0.f, 0.f, 0.f);
    int e = e0;
    for (; e + 3 < e1; e += 4) {
        int sa = g_src[e + half];
        int sb = g_src[e + 2 + half];
        float qa = (hl < 5) ? g_ea5[(size_t)(e + half) * 5 + hl] : 0.f;
        float qb = (hl < 5) ? g_ea5[(size_t)(e + 2 + half) * 5 + hl] : 0.f;
        float4 va = *(const float4*)(XS + (size_t)sa * 64 + c0);
        float4 vb = *(const float4*)(XS + (size_t)sb * 64 + c0);
        float pa0 = xd.x + va.x, pa1 = xd.y + va.y, pa2 = xd.z + va.z, pa3 = xd.w + va.w;
        float pb0 = xd.x + vb.x, pb1 = xd.y + vb.y, pb2 = xd.z + vb.z, pb3 = xd.w + vb.w;
        #pragma unroll
        for (int k = 0; k < 5; ++k) {
            float ea = __shfl_sync(0xffffffffu, qa, k, 16);
            float eb = __shfl_sync(0xffffffffu, qb, k, 16);
            pa0 += ea * we[k].x; pa1 += ea * we[k].y; pa2 += ea * we[k].z; pa3 += ea * we[k].w;
            pb0 += eb * we[k].x; pb1 += eb * we[k].y; pb2 += eb * we[k].z; pb3 += eb * we[k].w;
        }
        acc.x += fmaxf(pa0, 0.f) + fmaxf(pb0, 0.f);
        acc.y += fmaxf(pa1, 0.f) + fmaxf(pb1, 0.f);
        acc.z += fmaxf(pa2, 0.f) + fmaxf(pb2, 0.f);
        acc.w += fmaxf(pa3, 0.f) + fmaxf(pb3, 0.f);
    }
    for (; e + 1 < e1; e += 2) {
        int s = g_src[e + half];
        float q = (hl < 5) ? g_ea5[(size_t)(e + half) * 5 + hl] : 0.f;
        float4 v = *(const float4*)(XS + (size_t)s * 64 + c0);
        float p0 = xd.x + v.x, p1 = xd.y + v.y, p2 = xd.z + v.z, p3 = xd.w + v.w;
        #pragma unroll
        for (int k = 0; k < 5; ++k) {
            float ek = __shfl_sync(0xffffffffu, q, k, 16);
            p0 += ek * we[k].x; p1 += ek * we[k].y; p2 += ek * we[k].z; p3 += ek * we[k].w;
        }
        acc.x += fmaxf(p0, 0.f); acc.y += fmaxf(p1, 0.f);
        acc.z += fmaxf(p2, 0.f); acc.w += fmaxf(p3, 0.f);
    }
    if (e < e1) {
        int s = g_src[e];
        float q = (hl < 5) ? g_ea5[(size_t)e * 5 + hl] : 0.f;
        float4 v = *(const float4*)(XS + (size_t)s * 64 + c0);
        float p0 = xd.x + v.x, p1 = xd.y + v.y, p2 = xd.z + v.z, p3 = xd.w + v.w;
        #pragma unroll
        for (int k = 0; k < 5; ++k) {
            float ek = __shfl_sync(0xffffffffu, q, k, 16);
            p0 += ek * we[k].x; p1 += ek * we[k].y; p2 += ek * we[k].z; p3 += ek * we[k].w;
        }
        if (half == 0) {
            acc.x += fmaxf(p0, 0.f); acc.y += fmaxf(p1, 0.f);
            acc.z += fmaxf(p2, 0.f); acc.w += fmaxf(p3, 0.f);
        }
    }
    acc.x += __shfl_xor_sync(0xffffffffu, acc.x, 16);
    acc.y += __shfl_xor_sync(0xffffffffu, acc.y, 16);
    acc.z += __shfl_xor_sync(0xffffffffu, acc.z, 16);
    acc.w += __shfl_xor_sync(0xffffffffu, acc.w, 16);
    if (half == 0)
        *(float4*)(&sRow[w][c0]) = acc;
    __syncwarp();
    // GEMV: out[v][c] = relu( row@W2[:,c] + deg*b2[c] ), 2 cols per lane
    {
        int c = lane * 2;
        float a0 = 0.f, a1 = 0.f;
        #pragma unroll 8
        for (int k = 0; k < 64; ++k) {
            float h = sRow[w][k];
            float2 wv = *(const float2*)(sW2 + k * 64 + c);
            a0 += h * wv.x; a1 += h * wv.y;
        }
        float dg = g_deg[wid];
        a0 += dg * b2[c];
        a1 += dg * b2[c + 1];
        float2 o;
        o.x = fmaxf(a0, 0.f);
        o.y = fmaxf(a1, 0.f);
        *(float2*)(out + (size_t)wid * 64 + c) = o;
    }
}

// final-layer edge aggregation (no gemv; feeds 64x6 post) — R8 version
__global__ void __launch_bounds__(256)
k_edge(const float* __restrict__ XDb, const float* __restrict__ XS,
       const float* __restrict__ W1e, float* __restrict__ agg)
{
    __shared__ float sE[5 * 64];
    int tid = threadIdx.x;
    for (int i = tid; i < 5 * 64; i += 256) sE[i] = W1e[i];
    __syncthreads();
    int wid = (blockIdx.x * 256 + tid) >> 5;
    int lane = tid & 31;
    if (wid >= NN) return;
    int half = lane >> 4;
    int hl = lane & 15;
    int c0 = hl * 4;
    float4 xd = *(const float4*)(XDb + (size_t)wid * 64 + c0);
    float4 we[5];
    #pragma unroll
    for (int k = 0; k < 5; ++k) we[k] = *(const float4*)(sE + k * 64 + c0);
    int e0 = g_ptr[wid], e1 = g_ptr[wid + 1];
    float4 acc = make_float4(0.f, 0.f, 0.f, 0.f);
    int e = e0;
    for (; e + 3 < e1; e += 4) {
        int sa = g_src[e + half];
        int sb = g_src[e + 2 + half];
        float qa = (hl < 5) ? g_ea5[(size_t)(e + half) * 5 + hl] : 0.f;
        float qb = (hl < 5) ? g_ea5[(size_t)(e + 2 + half) * 5 + hl] : 0.f;
        float4 va = *(const float4*)(XS + (size_t)sa * 64 + c0);
        float4 vb = *(const float4*)(XS + (size_t)sb * 64 + c0);
        float pa0 = xd.x + va.x, pa1 = xd.y + va.y, pa2 = xd.z + va.z, pa3 = xd.w + va.w;
        float pb0 = xd.x + vb.x, pb1 = xd.y + vb.y, pb2 = xd.z + vb.z, pb3 = xd.w + vb.w;
        #pragma unroll
        for (int k = 0; k < 5; ++k) {
            float ea = __shfl_sync(0xffffffffu, qa, k, 16);
            float eb = __shfl_sync(0xffffffffu, qb, k, 16);
            pa0 += ea * we[k].x; pa1 += ea * we[k].y; pa2 += ea * we[k].z; pa3 += ea * we[k].w;
            pb0 += eb * we[k].x; pb1 += eb * we[k].y; pb2 += eb * we[k].z; pb3 += eb * we[k].w;
        }
        acc.x += fmaxf(pa0, 0.f) + fmaxf(pb0, 0.f);
        acc.y += fmaxf(pa1, 0.f) + fmaxf(pb1, 0.f);
        acc.z += fmaxf(pa2, 0.f) + fmaxf(pb2, 0.f);
        acc.w += fmaxf(pa3, 0.f) + fmaxf(pb3, 0.f);
    }
    for (; e + 1 < e1; e += 2) {
        int s = g_src[e + half];
        float q = (hl < 5) ? g_ea5[(size_t)(e + half) * 5 + hl] : 0.f;
        float4 v = *(const float4*)(XS + (size_t)s * 64 + c0);
        float p0 = xd.x + v.x, p1 = xd.y + v.y, p2 = xd.z + v.z, p3 = xd.w + v.w;
        #pragma unroll
        for (int k = 0; k < 5; ++k) {
            float ek = __shfl_sync(0xffffffffu, q, k, 16);
            p0 += ek * we[k].x; p1 += ek * we[k].y; p2 += ek * we[k].z; p3 += ek * we[k].w;
        }
        acc.x += fmaxf(p0, 0.f); acc.y += fmaxf(p1, 0.f);
        acc.z += fmaxf(p2, 0.f); acc.w += fmaxf(p3, 0.f);
    }
    if (e < e1) {
        int s = g_src[e];
        float q = (hl < 5) ? g_ea5[(size_t)e * 5 + hl] : 0.f;
        float4 v = *(const float4*)(XS + (size_t)s * 64 + c0);
        float p0 = xd.x + v.x, p1 = xd.y + v.y, p2 = xd.z + v.z, p3 = xd.w + v.w;
        #pragma unroll
        for (int k = 0; k < 5; ++k) {
            float ek = __shfl_sync(0xffffffffu, q, k, 16);
            p0 += ek * we[k].x; p1 += ek * we[k].y; p2 += ek * we[k].z; p3 += ek * we[k].w;
        }
        if (half == 0) {
            acc.x += fmaxf(p0, 0.f); acc.y += fmaxf(p1, 0.f);
            acc.z += fmaxf(p2, 0.f); acc.w += fmaxf(p3, 0.f);
        }
    }
    acc.x += __shfl_xor_sync(0xffffffffu, acc.x, 16);
    acc.y += __shfl_xor_sync(0xffffffffu, acc.y, 16);
    acc.z += __shfl_xor_sync(0xffffffffu, acc.z, 16);
    acc.w += __shfl_xor_sync(0xffffffffu, acc.w, 16);
    if (half == 0)
        *(float4*)(agg + (size_t)wid * 64 + c0) = acc;
}

// TAGConv propagation hop + fused GEMV:
//   h_out[v] = dis[v] * sum_e dis[src_e] * H_in[src_e]     (written if Hout)
//   accOut[v][c] = (accIn? accIn[v][c]:0) + h_out[v]@Whop[:,c]
//                  (+ Hin[v]@Wdir[:,c] if Wdir)  (+ bias[c] if bias) (relu opt)
__global__ void __launch_bounds__(256)
k_prop_gemv(const float* __restrict__ Hin, float* __restrict__ Hout,
            const float* __restrict__ Wdir, const float* __restrict__ Whop,
            const float* __restrict__ accIn, float* __restrict__ accOut,
            const float* __restrict__ bias, int do_relu)
{
    __shared__ float sWh[64 * 64];
    __shared__ float sWd[64 * 64];
    __shared__ float sRow[8][64];
    __shared__ float sXr[8][64];
    int tid = threadIdx.x;
    {
        const float4* Wv = (const float4*)Whop;
        #pragma unroll
        for (int i = 0; i < 4; ++i)
            ((float4*)sWh)[tid + i * 256] = Wv[tid + i * 256];
        if (Wdir) {
            const float4* Wd = (const float4*)Wdir;
            #pragma unroll
            for (int i = 0; i < 4; ++i)
                ((float4*)sWd)[tid + i * 256] = Wd[tid + i * 256];
        }
    }
    __syncthreads();
    int wid = (blockIdx.x * 256 + tid) >> 5;
    int lane = tid & 31;
    int w = tid >> 5;
    if (wid >= NN) return;
    int half = lane >> 4;
    int hl = lane & 15;
    int c0 = hl * 4;
    float dd = g_dis[wid];
    int e0 = g_ptr[wid], e1 = g_ptr[wid + 1];
    float4 acc = make_float4(0.f, 0.f, 0.f, 0.f);
    int e = e0;
    for (; e + 7 < e1; e += 8) {
        int s0 = g_src[e + half];
        int s1 = g_src[e + 2 + half];
        int s2 = g_src[e + 4 + half];
        int s3 = g_src[e + 6 + half];
        float n0 = g_dis[s0], n1 = g_dis[s1], n2 = g_dis[s2], n3 = g_dis[s3];
        float4 v0 = *(const float4*)(Hin + (size_t)s0 * 64 + c0);
        float4 v1 = *(const float4*)(Hin + (size_t)s1 * 64 + c0);
        float4 v2 = *(const float4*)(Hin + (size_t)s2 * 64 + c0);
        float4 v3 = *(const float4*)(Hin + (size_t)s3 * 64 + c0);
        acc.x += n0 * v0.x + n1 * v1.x + n2 * v2.x + n3 * v3.x;
        acc.y += n0 * v0.y + n1 * v1.y + n2 * v2.y + n3 * v3.y;
        acc.z += n0 * v0.z + n1 * v1.z + n2 * v2.z + n3 * v3.z;
        acc.w += n0 * v0.w + n1 * v1.w + n2 * v2.w + n3 * v3.w;
    }
    for (; e + 1 < e1; e += 2) {
        int s = g_src[e + half];
        float nr = g_dis[s];
        float4 v = *(const float4*)(Hin + (size_t)s * 64 + c0);
        acc.x += nr * v.x; acc.y += nr * v.y;
        acc.z += nr * v.z; acc.w += nr * v.w;
    }
    if (e < e1 && half == 0) {
        int s = g_src[e];
        float nr = g_dis[s];
        float4 v = *(const float4*)(Hin + (size_t)s * 64 + c0);
        acc.x += nr * v.x; acc.y += nr * v.y;
        acc.z += nr * v.z; acc.w += nr * v.w;
    }
    acc.x += __shfl_xor_sync(0xffffffffu, acc.x, 16);
    acc.y += __shfl_xor_sync(0xffffffffu, acc.y, 16);
    acc.z += __shfl_xor_sync(0xffffffffu, acc.z, 16);
    acc.w += __shfl_xor_sync(0xffffffffu, acc.w, 16);
    if (half == 0) {
        float4 o = make_float4(dd * acc.x, dd * acc.y, dd * acc.z, dd * acc.w);
        *(float4*)(&sRow[w][c0]) = o;
        if (Hout) *(float4*)(Hout + (size_t)wid * 64 + c0) = o;
    }
    // stage direct row (x[v]) if Wdir
    if (Wdir) {
        float2 xv = *(const float2*)(Hin + (size_t)wid * 64 + lane * 2);
        *(float2*)(&sXr[w][lane * 2]) = xv;
    }
    __syncwarp();
    // GEMV epilogue, 2 cols per lane
    {
        int c = lane * 2;
        float a0 = 0.f, a1 = 0.f;
        if (Wdir) {
            #pragma unroll 8
            for (int k = 0; k < 64; ++k) {
                float h = sRow[w][k];
                float xv = sXr[w][k];
                float2 wh = *(const float2*)(sWh + k * 64 + c);
                float2 wd = *(const float2*)(sWd + k * 64 + c);
                a0 += h * wh.x + xv * wd.x;
                a1 += h * wh.y + xv * wd.y;
            }
        } else {
            #pragma unroll 8
            for (int k = 0; k < 64; ++k) {
                float h = sRow[w][k];
                float2 wh = *(const float2*)(sWh + k * 64 + c);
                a0 += h * wh.x; a1 += h * wh.y;
            }
        }
        if (accIn) {
            float2 ai = *(const float2*)(accIn + (size_t)wid * 64 + c);
            a0 += ai.x; a1 += ai.y;
        }
        if (bias) { a0 += bias[c]; a1 += bias[c + 1]; }
        if (do_relu) { a0 = fmaxf(a0, 0.f); a1 = fmaxf(a1, 0.f); }
        *(float2*)(accOut + (size_t)wid * 64 + c) = make_float2(a0, a1);
    }
}

// final layer post: out[v][c] = agg[v][:]@W2[:,c] + deg[v]*b2[c]   (64x6, no relu)
__global__ void __launch_bounds__(192)
k_post_last(const float* __restrict__ agg, const float* __restrict__ W2,
            const float* __restrict__ b2, float* __restrict__ out)
{
    __shared__ float sW[64 * 6];
    __shared__ float sb[6];
    int tid = threadIdx.x;
    for (int i = tid; i < 64 * 6; i += 192) sW[i] = W2[i];
    if (tid < 6) sb[tid] = b2[tid];
    __syncthreads();
    int gid = blockIdx.x * 192 + tid;
    int v = gid / 6;
    int c = gid - v * 6;
    if (v >= NN) return;
    const float* ar = agg + (size_t)v * 64;
    float acc = 0.f;
    #pragma unroll
    for (int k = 0; k < 64; ++k) acc += ar[k] * sW[k * 6 + c];
    out[v * 6 + c] = acc + g_deg[v] * sb[c];
}

// ---------------- host ----------------

extern "C" void kernel_launch(void* const* d_in, const int* in_sizes, int n_in,
                              void* d_out, int out_size)
{
    const float* data_x     = (const float*)d_in[0];
    const int*   edge_index = (const int*)  d_in[1];
    const float* edge_attr  = (const float*)d_in[2];
    const float* ea0_W1     = (const float*)d_in[3];
    const float* ea0_b1     = (const float*)d_in[4];
    const float* ea0_W2     = (const float*)d_in[5];
    const float* ea0_b2     = (const float*)d_in[6];
    const float* eam_W1     = (const float*)d_in[7];
    const float* eam_b1     = (const float*)d_in[8];
    const float* eam_W2     = (const float*)d_in[9];
    const float* eam_b2     = (const float*)d_in[10];
    const float* eal_W1     = (const float*)d_in[11];
    const float* eal_b1     = (const float*)d_in[12];
    const float* eal_W2     = (const float*)d_in[13];
    const float* eal_b2     = (const float*)d_in[14];
    const float* tag_W      = (const float*)d_in[15];
    const float* tag_b      = (const float*)d_in[16];
    float* out = (float*)d_out;

    float* pBuf = nullptr;
    cudaGetSymbolAddress((void**)&pBuf, g_buf);
    float* B0 = pBuf + 0 * (size_t)NN * HH;
    float* B1 = pBuf + 1 * (size_t)NN * HH;
    float* B2 = pBuf + 2 * (size_t)NN * HH;
    float* B3 = pBuf + 3 * (size_t)NN * HH;
    float* B4 = pBuf + 4 * (size_t)NN * HH;

    const int EB = (EE + 255) / 256;
    const int WB = (NN * 32 + 255) / 256;
    const int GB = (NN + 63) / 64;

    // CSR build
    k_zero_counts<<<(NN + 255) / 256, 256>>>();
    k_count<<<EB, 256>>>(edge_index);
    k_scan<<<1, 1024>>>();
    k_scatter<<<EB, 256>>>(edge_index, edge_attr);

    // layer 1: edge_agg ea0 (x = data_x[:,4:10]) with fused W2 epilogue
    k_pre0<<<(NN * 128 + 255) / 256, 256>>>(data_x, ea0_W1, ea0_b1, B0, B1);
    k_edge_gemv<<<WB, 256>>>(B0, B1, ea0_W1 + 12 * 64, ea0_W2, ea0_b2, B3);
    float* x = B3;

    for (int l = 0; l < 3; ++l) {
        const float* Wl = tag_W + (size_t)l * 4 * 64 * 64;
        const float* bl = tag_b + l * 64;
        // P1: h1 = prop(x) -> B0 ; acc = x@W0 + h1@W1 -> B2
        k_prop_gemv<<<WB, 256>>>(x, B0, Wl /*W0*/, Wl + 64 * 64 /*W1*/,
                                 nullptr, B2, nullptr, 0);
        // P2: h2 = prop(h1) -> B1 ; acc += h2@W2
        k_prop_gemv<<<WB, 256>>>(B0, B1, nullptr, Wl + 2 * 64 * 64,
                                 B2, B2, nullptr, 0);
        // P3: h3 = prop(h2) ; out = acc + h3@W3 + b, relu -> B4
        k_prop_gemv<<<WB, 256>>>(B1, nullptr, nullptr, Wl + 3 * 64 * 64,
                                 B2, B4, bl, 1);
        x = B4;

        if (l < 2) {
            // mid edge_agg l with fused W2 epilogue
            const float* W1 = eam_W1 + (size_t)l * 133 * 64;
            const float* b1 = eam_b1 + l * 64;
            const float* W2 = eam_W2 + (size_t)l * 64 * 64;
            const float* b2 = eam_b2 + l * 64;
            k_gemm64_dual<<<GB, 256>>>(x, W1, b1, W1 + 64 * 64, B0, B1, NN);
            k_edge_gemv<<<WB, 256>>>(B0, B1, W1 + 128 * 64, W2, b2, B3);
            x = B3;
        }
    }

    // final edge_agg (64 -> 6)
    k_gemm64_dual<<<GB, 256>>>(x, eal_W1, eal_b1, eal_W1 + 64 * 64, B0, B1, NN);
    k_edge<<<WB, 256>>>(B0, B1, eal_W1 + 128 * 64, B2);
    k_post_last<<<(NN * 6 + 191) / 192, 192>>>(B2, eal_W2, eal_b2, out);
}

// round 15
// speedup vs baseline: 1.2160x; 1.2160x over previous
#include <cuda_runtime.h>
#include <cuda_fp16.h>
#include <stdint.h>
#include <math.h>

#define NN 20000
#define EE 320000
#define E2 (2*EE)
#define HH 64

// ---------------- static scratch (no allocations allowed) ----------------
__device__ int   g_cnt[NN];
__device__ int   g_ptr[NN + 1];
__device__ int   g_rank[E2];
__device__ int   g_src[E2];
__device__ float g_ea5[E2 * 5];
__device__ float g_deg[NN];
__device__ float g_dis[NN];
__device__ float g_buf[5][NN * HH];

// ---------------- setup kernels ----------------

__global__ void k_count(const int* __restrict__ ei)
{
    int j = blockIdx.x * blockDim.x + threadIdx.x;
    if (j >= EE) return;
    int a = ei[j], b = ei[EE + j];
    int r0 = atomicAdd(&g_cnt[b], 1);
    int r1 = atomicAdd(&g_cnt[a], 1);
    g_rank[j]      = r0;
    g_rank[EE + j] = r1;
}

__global__ void k_scan()
{
    __shared__ int sw[32];
    __shared__ int sTotal;
    __shared__ int sCarry;
    int t = threadIdx.x;
    int lane = t & 31, w = t >> 5;
    if (t == 0) sCarry = 0;
    for (int base = 0; base < NN; base += 1024) {
        __syncthreads();
        int carry = sCarry;
        int i = base + t;
        int v = (i < NN) ? g_cnt[i] : 0;
        int x = v;
        #pragma unroll
        for (int d = 1; d < 32; d <<= 1) {
            int y = __shfl_up_sync(0xffffffffu, x, d);
            if (lane >= d) x += y;
        }
        if (lane == 31) sw[w] = x;
        __syncthreads();
        if (w == 0) {
            int y = sw[lane];
            #pragma unroll
            for (int d = 1; d < 32; d <<= 1) {
                int z = __shfl_up_sync(0xffffffffu, y, d);
                if (lane >= d) y += z;
            }
            sw[lane] = y;
            if (lane == 31) sTotal = y;
        }
        __syncthreads();
        int incl = x + ((w > 0) ? sw[w - 1] : 0);
        if (i < NN) {
            g_ptr[i] = carry + incl - v;
            float df = (float)v;
            g_deg[i] = df;
            g_dis[i] = (v > 0) ? rsqrtf(df) : 0.f;
        }
        __syncthreads();
        if (t == 0) sCarry = carry + sTotal;
    }
    __syncthreads();
    if (t == 0) g_ptr[NN] = sCarry;
}

__global__ void k_scatter(const int* __restrict__ ei, const float* __restrict__ eattr)
{
    int j = blockIdx.x * blockDim.x + threadIdx.x;
    if (j >= EE) return;
    int a = ei[j], b = ei[EE + j];
    float e0 = eattr[j * 5 + 0];
    float e1 = eattr[j * 5 + 1];
    float e2 = eattr[j * 5 + 2];
    float e3 = eattr[j * 5 + 3];
    float e4 = eattr[j * 5 + 4];
    int p0 = g_ptr[b] + g_rank[j];
    int p1 = g_ptr[a] + g_rank[EE + j];
    g_src[p0] = a;
    g_src[p1] = b;
    float* q0 = g_ea5 + (size_t)p0 * 5;
    q0[0] = e0; q0[1] = e1; q0[2] = e2; q0[3] = e3; q0[4] = e4;
    float* q1 = g_ea5 + (size_t)p1 * 5;
    q1[0] = e0; q1[1] = e1; q1[2] = e2; q1[3] = e3; q1[4] = e4;
}

// ---------------- layer kernels ----------------

// first layer pre: XDb = x@W1[0:6]+b1, XS = x@W1[6:12]  (x = data_x[:,4:10])
__global__ void k_pre0(const float* __restrict__ data_x,
                       const float* __restrict__ W1, const float* __restrict__ b1,
                       float* __restrict__ XDb, float* __restrict__ XS)
{
    __shared__ float sW[12 * 64];
    int tid = threadIdx.x;
    for (int i = tid; i < 12 * 64; i += 256) sW[i] = W1[i];
    __syncthreads();
    int gid = blockIdx.x * 256 + tid;
    int v = gid >> 7;
    int j = gid & 127;
    if (v >= NN) return;
    const float* xr = data_x + v * 16 + 4;
    float x0 = xr[0], x1 = xr[1], x2 = xr[2], x3 = xr[3], x4 = xr[4], x5 = xr[5];
    if (j < 64) {
        float acc = b1[j];
        acc += x0 * sW[0 * 64 + j]; acc += x1 * sW[1 * 64 + j];
        acc += x2 * sW[2 * 64 + j]; acc += x3 * sW[3 * 64 + j];
        acc += x4 * sW[4 * 64 + j]; acc += x5 * sW[5 * 64 + j];
        XDb[v * 64 + j] = acc;
    } else {
        int c = j - 64;
        float acc = 0.f;
        acc += x0 * sW[6 * 64 + c];  acc += x1 * sW[7 * 64 + c];
        acc += x2 * sW[8 * 64 + c];  acc += x3 * sW[9 * 64 + c];
        acc += x4 * sW[10 * 64 + c]; acc += x5 * sW[11 * 64 + c];
        XS[v * 64 + c] = acc;
    }
}

// generic fp32 GEMM (R8 version): out = act( sum_seg A_seg@W_seg + bias*scale )
__global__ void __launch_bounds__(256)
k_gemm64(const float* A0, const float* A1, const float* A2, const float* A3,
         int nA, const float* __restrict__ W, const float* __restrict__ bias,
         const float* __restrict__ degscale, float* __restrict__ out,
         int do_relu, int n)
{
    __shared__ __align__(16) float sW[64 * 64];
    __shared__ __align__(16) float sA[64 * 68];
    const int tid = threadIdx.x;
    const int rowBase = blockIdx.x * 64;
    const int c0 = (tid & 15) * 4;
    const int r0 = (tid >> 4) * 4;
    float acc[4][4] = {};
    const float* As[4] = {A0, A1, A2, A3};

    for (int seg = 0; seg < nA; ++seg) {
        const float* A = As[seg];
        const float4* Wv = (const float4*)(W + seg * 64 * 64);
        #pragma unroll
        for (int i = 0; i < 4; ++i)
            ((float4*)sW)[tid + i * 256] = Wv[tid + i * 256];
        int lr = tid >> 4;
        int lc = (tid & 15) * 4;
        #pragma unroll
        for (int i = 0; i < 4; ++i) {
            int r = lr + i * 16;
            int gr = rowBase + r;
            float4 v = make_float4(0.f, 0.f, 0.f, 0.f);
            if (gr < n) v = *(const float4*)(A + (size_t)gr * 64 + lc);
            *(float4*)(&sA[r * 68 + lc]) = v;
        }
        __syncthreads();
        #pragma unroll
        for (int k = 0; k < 64; ++k) {
            float4 b = *(const float4*)(&sW[k * 64 + c0]);
            float a0 = sA[(r0 + 0) * 68 + k];
            float a1 = sA[(r0 + 1) * 68 + k];
            float a2 = sA[(r0 + 2) * 68 + k];
            float a3 = sA[(r0 + 3) * 68 + k];
            acc[0][0] += a0 * b.x; acc[0][1] += a0 * b.y; acc[0][2] += a0 * b.z; acc[0][3] += a0 * b.w;
            acc[1][0] += a1 * b.x; acc[1][1] += a1 * b.y; acc[1][2] += a1 * b.z; acc[1][3] += a1 * b.w;
            acc[2][0] += a2 * b.x; acc[2][1] += a2 * b.y; acc[2][2] += a2 * b.z; acc[2][3] += a2 * b.w;
            acc[3][0] += a3 * b.x; acc[3][1] += a3 * b.y; acc[3][2] += a3 * b.z; acc[3][3] += a3 * b.w;
        }
        __syncthreads();
    }

    float4 bv = make_float4(0.f, 0.f, 0.f, 0.f);
    if (bias) bv = *(const float4*)(bias + c0);
    #pragma unroll
    for (int i = 0; i < 4; ++i) {
        int gr = rowBase + r0 + i;
        if (gr < n) {
            float s = degscale ? degscale[gr] : 1.0f;
            float4 o;
            o.x = acc[i][0] + bv.x * s;
            o.y = acc[i][1] + bv.y * s;
            o.z = acc[i][2] + bv.z * s;
            o.w = acc[i][3] + bv.w * s;
            if (do_relu) {
                o.x = fmaxf(o.x, 0.f); o.y = fmaxf(o.y, 0.f);
                o.z = fmaxf(o.z, 0.f); o.w = fmaxf(o.w, 0.f);
            }
            *(float4*)(out + (size_t)gr * 64 + c0) = o;
        }
    }
}

// dual GEMM (R8 version): out0 = A@Wa + ba, out1 = A@Wb
__global__ void __launch_bounds__(256)
k_gemm64_dual(const float* __restrict__ A, const float* __restrict__ Wa,
              const float* __restrict__ ba, const float* __restrict__ Wb,
              float* __restrict__ out0, float* __restrict__ out1, int n)
{
    __shared__ __align__(16) float sW[64 * 64];
    __shared__ __align__(16) float sA[64 * 68];
    const int tid = threadIdx.x;
    const int rowBase = blockIdx.x * 64;
    const int c0 = (tid & 15) * 4;
    const int r0 = (tid >> 4) * 4;
    const int lr = tid >> 4;
    const int lc = (tid & 15) * 4;

    #pragma unroll
    for (int i = 0; i < 4; ++i) {
        int r = lr + i * 16;
        int gr = rowBase + r;
        float4 v = make_float4(0.f, 0.f, 0.f, 0.f);
        if (gr < n) v = *(const float4*)(A + (size_t)gr * 64 + lc);
        *(float4*)(&sA[r * 68 + lc]) = v;
    }

    #pragma unroll
    for (int half = 0; half < 2; ++half) {
        const float4* Wv = (const float4*)(half ? Wb : Wa);
        #pragma unroll
        for (int i = 0; i < 4; ++i)
            ((float4*)sW)[tid + i * 256] = Wv[tid + i * 256];
        __syncthreads();
        float acc[4][4] = {};
        #pragma unroll
        for (int k = 0; k < 64; ++k) {
            float4 b = *(const float4*)(&sW[k * 64 + c0]);
            float a0 = sA[(r0 + 0) * 68 + k];
            float a1 = sA[(r0 + 1) * 68 + k];
            float a2 = sA[(r0 + 2) * 68 + k];
            float a3 = sA[(r0 + 3) * 68 + k];
            acc[0][0] += a0 * b.x; acc[0][1] += a0 * b.y; acc[0][2] += a0 * b.z; acc[0][3] += a0 * b.w;
            acc[1][0] += a1 * b.x; acc[1][1] += a1 * b.y; acc[1][2] += a1 * b.z; acc[1][3] += a1 * b.w;
            acc[2][0] += a2 * b.x; acc[2][1] += a2 * b.y; acc[2][2] += a2 * b.z; acc[2][3] += a2 * b.w;
            acc[3][0] += a3 * b.x; acc[3][1] += a3 * b.y; acc[3][2] += a3 * b.z; acc[3][3] += a3 * b.w;
        }
        float4 bv = make_float4(0.f, 0.f, 0.f, 0.f);
        if (half == 0 && ba) bv = *(const float4*)(ba + c0);
        float* outp = half ? out1 : out0;
        #pragma unroll
        for (int i = 0; i < 4; ++i) {
            int gr = rowBase + r0 + i;
            if (gr < n) {
                float4 o;
                o.x = acc[i][0] + bv.x; o.y = acc[i][1] + bv.y;
                o.z = acc[i][2] + bv.z; o.w = acc[i][3] + bv.w;
                *(float4*)(outp + (size_t)gr * 64 + c0) = o;
            }
        }
        __syncthreads();
    }
}

// edge-body helper: acc(float4) = sum_e relu(xd + XS[src] + ea@W1e) for node wid,
// half-warp per edge, 8-edge main loop; result reduced across halves.
__device__ __forceinline__ float4
edge_body(int wid, int half, int hl, int c0,
          const float* __restrict__ XDb, const float* __restrict__ XS,
          const float* __restrict__ sE)
{
    float4 xd = *(const float4*)(XDb + (size_t)wid * 64 + c0);
    float4 w[5];
    #pragma unroll
    for (int k = 0; k < 5; ++k) w[k] = *(const float4*)(sE + k * 64 + c0);
    int e0 = g_ptr[wid], e1 = g_ptr[wid + 1];
    float4 acc = make_float4(0.f, 0.f, 0.f, 0.f);
    int e = e0;
    // 4 pairs (8 edges) per iteration
    for (; e + 7 < e1; e += 8) {
        int s0 = g_src[e + half];
        int s1 = g_src[e + 2 + half];
        int s2 = g_src[e + 4 + half];
        int s3 = g_src[e + 6 + half];
        float q0 = (hl < 5) ? g_ea5[(size_t)(e + half) * 5 + hl] : 0.f;
        float q1 = (hl < 5) ? g_ea5[(size_t)(e + 2 + half) * 5 + hl] : 0.f;
        float q2 = (hl < 5) ? g_ea5[(size_t)(e + 4 + half) * 5 + hl] : 0.f;
        float q3 = (hl < 5) ? g_ea5[(size_t)(e + 6 + half) * 5 + hl] : 0.f;
        float4 v0 = *(const float4*)(XS + (size_t)s0 * 64 + c0);
        float4 v1 = *(const float4*)(XS + (size_t)s1 * 64 + c0);
        float4 v2 = *(const float4*)(XS + (size_t)s2 * 64 + c0);
        float4 v3 = *(const float4*)(XS + (size_t)s3 * 64 + c0);
        float p00 = xd.x + v0.x, p01 = xd.y + v0.y, p02 = xd.z + v0.z, p03 = xd.w + v0.w;
        float p10 = xd.x + v1.x, p11 = xd.y + v1.y, p12 = xd.z + v1.z, p13 = xd.w + v1.w;
        float p20 = xd.x + v2.x, p21 = xd.y + v2.y, p22 = xd.z + v2.z, p23 = xd.w + v2.w;
        float p30 = xd.x + v3.x, p31 = xd.y + v3.y, p32 = xd.z + v3.z, p33 = xd.w + v3.w;
        #pragma unroll
        for (int k = 0; k < 5; ++k) {
            float ek0 = __shfl_sync(0xffffffffu, q0, k, 16);
            float ek1 = __shfl_sync(0xffffffffu, q1, k, 16);
            float ek2 = __shfl_sync(0xffffffffu, q2, k, 16);
            float ek3 = __shfl_sync(0xffffffffu, q3, k, 16);
            p00 += ek0 * w[k].x; p01 += ek0 * w[k].y; p02 += ek0 * w[k].z; p03 += ek0 * w[k].w;
            p10 += ek1 * w[k].x; p11 += ek1 * w[k].y; p12 += ek1 * w[k].z; p13 += ek1 * w[k].w;
            p20 += ek2 * w[k].x; p21 += ek2 * w[k].y; p22 += ek2 * w[k].z; p23 += ek2 * w[k].w;
            p30 += ek3 * w[k].x; p31 += ek3 * w[k].y; p32 += ek3 * w[k].z; p33 += ek3 * w[k].w;
        }
        acc.x += fmaxf(p00, 0.f) + fmaxf(p10, 0.f) + fmaxf(p20, 0.f) + fmaxf(p30, 0.f);
        acc.y += fmaxf(p01, 0.f) + fmaxf(p11, 0.f) + fmaxf(p21, 0.f) + fmaxf(p31, 0.f);
        acc.z += fmaxf(p02, 0.f) + fmaxf(p12, 0.f) + fmaxf(p22, 0.f) + fmaxf(p32, 0.f);
        acc.w += fmaxf(p03, 0.f) + fmaxf(p13, 0.f) + fmaxf(p23, 0.f) + fmaxf(p33, 0.f);
    }
    // one pair (2 edges)
    for (; e + 1 < e1; e += 2) {
        int s = g_src[e + half];
        float q = (hl < 5) ? g_ea5[(size_t)(e + half) * 5 + hl] : 0.f;
        float4 v = *(const float4*)(XS + (size_t)s * 64 + c0);
        float p0 = xd.x + v.x, p1 = xd.y + v.y, p2 = xd.z + v.z, p3 = xd.w + v.w;
        #pragma unroll
        for (int k = 0; k < 5; ++k) {
            float ek = __shfl_sync(0xffffffffu, q, k, 16);
            p0 += ek * w[k].x; p1 += ek * w[k].y; p2 += ek * w[k].z; p3 += ek * w[k].w;
        }
        acc.x += fmaxf(p0, 0.f); acc.y += fmaxf(p1, 0.f);
        acc.z += fmaxf(p2, 0.f); acc.w += fmaxf(p3, 0.f);
    }
    // singleton
    if (e < e1) {
        int s = g_src[e];
        float q = (hl < 5) ? g_ea5[(size_t)e * 5 + hl] : 0.f;
        float4 v = *(const float4*)(XS + (size_t)s * 64 + c0);
        float p0 = xd.x + v.x, p1 = xd.y + v.y, p2 = xd.z + v.z, p3 = xd.w + v.w;
        #pragma unroll
        for (int k = 0; k < 5; ++k) {
            float ek = __shfl_sync(0xffffffffu, q, k, 16);
            p0 += ek * w[k].x; p1 += ek * w[k].y; p2 += ek * w[k].z; p3 += ek * w[k].w;
        }
        if (half == 0) {
            acc.x += fmaxf(p0, 0.f); acc.y += fmaxf(p1, 0.f);
            acc.z += fmaxf(p2, 0.f); acc.w += fmaxf(p3, 0.f);
        }
    }
    acc.x += __shfl_xor_sync(0xffffffffu, acc.x, 16);
    acc.y += __shfl_xor_sync(0xffffffffu, acc.y, 16);
    acc.z += __shfl_xor_sync(0xffffffffu, acc.z, 16);
    acc.w += __shfl_xor_sync(0xffffffffu, acc.w, 16);
    return acc;
}

// edge aggregation (mid layers): agg -> global
__global__ void __launch_bounds__(256)
k_edge(const float* __restrict__ XDb, const float* __restrict__ XS,
       const float* __restrict__ W1e, float* __restrict__ agg)
{
    __shared__ __align__(16) float sE[5 * 64];
    int tid = threadIdx.x;
    for (int i = tid; i < 5 * 64; i += 256) sE[i] = W1e[i];
    __syncthreads();
    int wid = (blockIdx.x * 256 + tid) >> 5;
    int lane = tid & 31;
    if (wid >= NN) return;
    int half = lane >> 4;
    int hl = lane & 15;
    int c0 = hl * 4;
    float4 acc = edge_body(wid, half, hl, c0, XDb, XS, sE);
    if (half == 0)
        *(float4*)(agg + (size_t)wid * 64 + c0) = acc;
}

// final-layer edge aggregation with fused 64x6 post-GEMV:
//   out[v][c] = agg[v]@W2[:,c] + deg[v]*b2[c]   (c in 0..5, no relu)
__global__ void __launch_bounds__(256)
k_edge_last(const float* __restrict__ XDb, const float* __restrict__ XS,
            const float* __restrict__ W1e, const float* __restrict__ W2,
            const float* __restrict__ b2, float* __restrict__ out)
{
    __shared__ __align__(16) float sRow[8][64];
    __shared__ __align__(16) float sE[5 * 64];
    __shared__ __align__(16) float sW2[64 * 6];
    __shared__ float sb2[6];
    int tid = threadIdx.x;
    for (int i = tid; i < 5 * 64; i += 256) sE[i] = W1e[i];
    for (int i = tid; i < 64 * 6; i += 256) sW2[i] = W2[i];
    if (tid < 6) sb2[tid] = b2[tid];
    __syncthreads();
    int wid = (blockIdx.x * 256 + tid) >> 5;
    int lane = tid & 31;
    int w = tid >> 5;
    if (wid >= NN) return;
    int half = lane >> 4;
    int hl = lane & 15;
    int c0 = hl * 4;
    float4 acc = edge_body(wid, half, hl, c0, XDb, XS, sE);
    if (half == 0)
        *(float4*)(&sRow[w][c0]) = acc;
    __syncwarp();
    if (lane < 6) {
        float dg = g_deg[wid];
        float a = dg * sb2[lane];
        #pragma unroll 8
        for (int k = 0; k < 64; ++k)
            a += sRow[w][k] * sW2[k * 6 + lane];
        out[(size_t)wid * 6 + lane] = a;
    }
}

// TAGConv propagation: Hn[v] = dis[v] * sum_e dis[src_e] * H[src_e]
// half-warp per edge, 16-edge main loop.
__global__ void __launch_bounds__(256)
k_prop(const float* __restrict__ H, float* __restrict__ Hn)
{
    int tid = threadIdx.x;
    int wid = (blockIdx.x * 256 + tid) >> 5;
    int lane = tid & 31;
    if (wid >= NN) return;
    int half = lane >> 4;
    int hl = lane & 15;
    int c0 = hl * 4;
    float dd = g_dis[wid];
    int e0 = g_ptr[wid], e1 = g_ptr[wid + 1];
    float4 acc = make_float4(0.f, 0.f, 0.f, 0.f);
    int e = e0;
    // 8 pairs (16 edges) per iteration
    for (; e + 15 < e1; e += 16) {
        int s[8];
        #pragma unroll
        for (int i = 0; i < 8; ++i) s[i] = g_src[e + 2 * i + half];
        float nm[8];
        #pragma unroll
        for (int i = 0; i < 8; ++i) nm[i] = g_dis[s[i]];
        float4 v[8];
        #pragma unroll
        for (int i = 0; i < 8; ++i) v[i] = *(const float4*)(H + (size_t)s[i] * 64 + c0);
        #pragma unroll
        for (int i = 0; i < 8; ++i) {
            acc.x += nm[i] * v[i].x; acc.y += nm[i] * v[i].y;
            acc.z += nm[i] * v[i].z; acc.w += nm[i] * v[i].w;
        }
    }
    for (; e + 1 < e1; e += 2) {
        int s = g_src[e + half];
        float nr = g_dis[s];
        float4 v = *(const float4*)(H + (size_t)s * 64 + c0);
        acc.x += nr * v.x; acc.y += nr * v.y;
        acc.z += nr * v.z; acc.w += nr * v.w;
    }
    if (e < e1 && half == 0) {
        int s = g_src[e];
        float nr = g_dis[s];
        float4 v = *(const float4*)(H + (size_t)s * 64 + c0);
        acc.x += nr * v.x; acc.y += nr * v.y;
        acc.z += nr * v.z; acc.w += nr * v.w;
    }
    acc.x += __shfl_xor_sync(0xffffffffu, acc.x, 16);
    acc.y += __shfl_xor_sync(0xffffffffu, acc.y, 16);
    acc.z += __shfl_xor_sync(0xffffffffu, acc.z, 16);
    acc.w += __shfl_xor_sync(0xffffffffu, acc.w, 16);
    if (half == 0) {
        float4 o = make_float4(dd * acc.x, dd * acc.y, dd * acc.z, dd * acc.w);
        *(float4*)(Hn + (size_t)wid * 64 + c0) = o;
    }
}

// ---------------- host ----------------

extern "C" void kernel_launch(void* const* d_in, const int* in_sizes, int n_in,
                              void* d_out, int out_size)
{
    const float* data_x     = (const float*)d_in[0];
    const int*   edge_index = (const int*)  d_in[1];
    const float* edge_attr  = (const float*)d_in[2];
    const float* ea0_W1     = (const float*)d_in[3];
    const float* ea0_b1     = (const float*)d_in[4];
    const float* ea0_W2     = (const float*)d_in[5];
    const float* ea0_b2     = (const float*)d_in[6];
    const float* eam_W1     = (const float*)d_in[7];
    const float* eam_b1     = (const float*)d_in[8];
    const float* eam_W2     = (const float*)d_in[9];
    const float* eam_b2     = (const float*)d_in[10];
    const float* eal_W1     = (const float*)d_in[11];
    const float* eal_b1     = (const float*)d_in[12];
    const float* eal_W2     = (const float*)d_in[13];
    const float* eal_b2     = (const float*)d_in[14];
    const float* tag_W      = (const float*)d_in[15];
    const float* tag_b      = (const float*)d_in[16];
    float* out = (float*)d_out;

    float* pBuf = nullptr;
    float* pDeg = nullptr;
    int*   pCnt = nullptr;
    cudaGetSymbolAddress((void**)&pBuf, g_buf);
    cudaGetSymbolAddress((void**)&pDeg, g_deg);
    cudaGetSymbolAddress((void**)&pCnt, g_cnt);
    float* B0 = pBuf + 0 * (size_t)NN * HH;
    float* B1 = pBuf + 1 * (size_t)NN * HH;
    float* B2 = pBuf + 2 * (size_t)NN * HH;
    float* B3 = pBuf + 3 * (size_t)NN * HH;
    float* B4 = pBuf + 4 * (size_t)NN * HH;

    const int EB = (EE + 255) / 256;
    const int WB = (NN * 32 + 255) / 256;
    const int GB = (NN + 63) / 64;

    // CSR build
    cudaMemsetAsync(pCnt, 0, NN * sizeof(int));
    k_count<<<EB, 256>>>(edge_index);
    k_scan<<<1, 1024>>>();
    k_scatter<<<EB, 256>>>(edge_index, edge_attr);

    // layer 1: edge_agg ea0  (x = data_x[:,4:10])
    k_pre0<<<(NN * 128 + 255) / 256, 256>>>(data_x, ea0_W1, ea0_b1, B0, B1);
    k_edge<<<WB, 256>>>(B0, B1, ea0_W1 + 12 * 64, B2);
    k_gemm64<<<GB, 256>>>(B2, nullptr, nullptr, nullptr, 1, ea0_W2, ea0_b2, pDeg, B3, 1, NN);
    float* x = B3;

    for (int l = 0; l < 3; ++l) {
        // tagconv l
        k_prop<<<WB, 256>>>(x, B0);
        k_prop<<<WB, 256>>>(B0, B1);
        k_prop<<<WB, 256>>>(B1, B2);
        k_gemm64<<<GB, 256>>>(x, B0, B1, B2, 4, tag_W + (size_t)l * 4 * 64 * 64,
                              tag_b + l * 64, nullptr, B4, 1, NN);
        x = B4;

        if (l < 2) {
            // mid edge_agg l
            const float* W1 = eam_W1 + (size_t)l * 133 * 64;
            const float* b1 = eam_b1 + l * 64;
            const float* W2 = eam_W2 + (size_t)l * 64 * 64;
            const float* b2 = eam_b2 + l * 64;
            k_gemm64_dual<<<GB, 256>>>(x, W1, b1, W1 + 64 * 64, B0, B1, NN);
            k_edge<<<WB, 256>>>(B0, B1, W1 + 128 * 64, B2);
            k_gemm64<<<GB, 256>>>(B2, nullptr, nullptr, nullptr, 1, W2, b2, pDeg, B3, 1, NN);
            x = B3;
        }
    }

    // final edge_agg (64 -> 6) with fused post-GEMV
    k_gemm64_dual<<<GB, 256>>>(x, eal_W1, eal_b1, eal_W1 + 64 * 64, B0, B1, NN);
    k_edge_last<<<WB, 256>>>(B0, B1, eal_W1 + 128 * 64, eal_W2, eal_b2, out);
}

// round 17
// speedup vs baseline: 1.2550x; 1.0321x over previous
#include <cuda_runtime.h>
#include <cuda_fp16.h>
#include <stdint.h>
#include <math.h>

#define NN 20000
#define EE 320000
#define E2 (2*EE)
#define HH 64

// ---------------- static scratch (no allocations allowed) ----------------
__device__ int   g_cnt[NN];
__device__ int   g_ptr[NN + 1];
__device__ int   g_rank[E2];
__device__ int   g_src[E2];
__device__ float g_ea5[E2 * 5];
__device__ float g_deg[NN];
__device__ float g_dis[NN];
__device__ float g_buf[6][NN * HH];

// ---------------- setup kernels ----------------

__global__ void k_count(const int* __restrict__ ei)
{
    int j = blockIdx.x * blockDim.x + threadIdx.x;
    if (j >= EE) return;
    int a = ei[j], b = ei[EE + j];
    int r0 = atomicAdd(&g_cnt[b], 1);
    int r1 = atomicAdd(&g_cnt[a], 1);
    g_rank[j]      = r0;
    g_rank[EE + j] = r1;
}

// vectorized single-block scan: 4 elements/thread, 5 outer iterations
__global__ void k_scan()
{
    __shared__ int sw[32];
    __shared__ int sTotal;
    __shared__ int sCarry;
    int t = threadIdx.x;
    int lane = t & 31, w = t >> 5;
    if (t == 0) sCarry = 0;
    for (int base = 0; base < NN; base += 4096) {
        __syncthreads();
        int carry = sCarry;
        int i = base + t * 4;
        int4 v = make_int4(0, 0, 0, 0);
        if (i + 3 < NN) {
            v = *(const int4*)(g_cnt + i);
        } else {
            if (i + 0 < NN) v.x = g_cnt[i + 0];
            if (i + 1 < NN) v.y = g_cnt[i + 1];
            if (i + 2 < NN) v.z = g_cnt[i + 2];
            if (i + 3 < NN) v.w = g_cnt[i + 3];
        }
        int tv = v.x + v.y + v.z + v.w;
        int x = tv;
        #pragma unroll
        for (int d = 1; d < 32; d <<= 1) {
            int y = __shfl_up_sync(0xffffffffu, x, d);
            if (lane >= d) x += y;
        }
        if (lane == 31) sw[w] = x;
        __syncthreads();
        if (w == 0) {
            int y = sw[lane];
            #pragma unroll
            for (int d = 1; d < 32; d <<= 1) {
                int z = __shfl_up_sync(0xffffffffu, y, d);
                if (lane >= d) y += z;
            }
            sw[lane] = y;
            if (lane == 31) sTotal = y;
        }
        __syncthreads();
        int incl = x + ((w > 0) ? sw[w - 1] : 0);
        int p0 = carry + incl - tv;
        int p1 = p0 + v.x;
        int p2 = p1 + v.y;
        int p3 = p2 + v.z;
        if (i + 3 < NN) {
            *(int4*)(g_ptr + i) = make_int4(p0, p1, p2, p3);
            float4 df = make_float4((float)v.x, (float)v.y, (float)v.z, (float)v.w);
            *(float4*)(g_deg + i) = df;
            float4 ds;
            ds.x = (v.x > 0) ? rsqrtf(df.x) : 0.f;
            ds.y = (v.y > 0) ? rsqrtf(df.y) : 0.f;
            ds.z = (v.z > 0) ? rsqrtf(df.z) : 0.f;
            ds.w = (v.w > 0) ? rsqrtf(df.w) : 0.f;
            *(float4*)(g_dis + i) = ds;
        } else {
            int pj[4] = {p0, p1, p2, p3};
            int vj[4] = {v.x, v.y, v.z, v.w};
            #pragma unroll
            for (int j = 0; j < 4; ++j) {
                if (i + j < NN) {
                    g_ptr[i + j] = pj[j];
                    float df = (float)vj[j];
                    g_deg[i + j] = df;
                    g_dis[i + j] = (vj[j] > 0) ? rsqrtf(df) : 0.f;
                }
            }
        }
        __syncthreads();
        if (t == 0) sCarry = carry + sTotal;
    }
    __syncthreads();
    if (t == 0) g_ptr[NN] = sCarry;
}

__global__ void k_scatter(const int* __restrict__ ei, const float* __restrict__ eattr)
{
    int j = blockIdx.x * blockDim.x + threadIdx.x;
    if (j >= EE) return;
    int a = ei[j], b = ei[EE + j];
    float e0 = eattr[j * 5 + 0];
    float e1 = eattr[j * 5 + 1];
    float e2 = eattr[j * 5 + 2];
    float e3 = eattr[j * 5 + 3];
    float e4 = eattr[j * 5 + 4];
    int p0 = g_ptr[b] + g_rank[j];
    int p1 = g_ptr[a] + g_rank[EE + j];
    g_src[p0] = a;
    g_src[p1] = b;
    float* q0 = g_ea5 + (size_t)p0 * 5;
    q0[0] = e0; q0[1] = e1; q0[2] = e2; q0[3] = e3; q0[4] = e4;
    float* q1 = g_ea5 + (size_t)p1 * 5;
    q1[0] = e0; q1[1] = e1; q1[2] = e2; q1[3] = e3; q1[4] = e4;
}

// ---------------- layer kernels ----------------

// first layer pre: XDb = x@W1[0:6]+b1, XS = x@W1[6:12]  (x = data_x[:,4:10])
__global__ void k_pre0(const float* __restrict__ data_x,
                       const float* __restrict__ W1, const float* __restrict__ b1,
                       float* __restrict__ XDb, float* __restrict__ XS)
{
    __shared__ float sW[12 * 64];
    int tid = threadIdx.x;
    for (int i = tid; i < 12 * 64; i += 256) sW[i] = W1[i];
    __syncthreads();
    int gid = blockIdx.x * 256 + tid;
    int v = gid >> 7;
    int j = gid & 127;
    if (v >= NN) return;
    const float* xr = data_x + v * 16 + 4;
    float x0 = xr[0], x1 = xr[1], x2 = xr[2], x3 = xr[3], x4 = xr[4], x5 = xr[5];
    if (j < 64) {
        float acc = b1[j];
        acc += x0 * sW[0 * 64 + j]; acc += x1 * sW[1 * 64 + j];
        acc += x2 * sW[2 * 64 + j]; acc += x3 * sW[3 * 64 + j];
        acc += x4 * sW[4 * 64 + j]; acc += x5 * sW[5 * 64 + j];
        XDb[v * 64 + j] = acc;
    } else {
        int c = j - 64;
        float acc = 0.f;
        acc += x0 * sW[6 * 64 + c];  acc += x1 * sW[7 * 64 + c];
        acc += x2 * sW[8 * 64 + c];  acc += x3 * sW[9 * 64 + c];
        acc += x4 * sW[10 * 64 + c]; acc += x5 * sW[11 * 64 + c];
        XS[v * 64 + c] = acc;
    }
}

// generic fp32 GEMM (R8 version): out = act( sum_seg A_seg@W_seg + bias*scale )
__global__ void __launch_bounds__(256)
k_gemm64(const float* A0, const float* A1, const float* A2, const float* A3,
         int nA, const float* __restrict__ W, const float* __restrict__ bias,
         const float* __restrict__ degscale, float* __restrict__ out,
         int do_relu, int n)
{
    __shared__ __align__(16) float sW[64 * 64];
    __shared__ __align__(16) float sA[64 * 68];
    const int tid = threadIdx.x;
    const int rowBase = blockIdx.x * 64;
    const int c0 = (tid & 15) * 4;
    const int r0 = (tid >> 4) * 4;
    float acc[4][4] = {};
    const float* As[4] = {A0, A1, A2, A3};

    for (int seg = 0; seg < nA; ++seg) {
        const float* A = As[seg];
        const float4* Wv = (const float4*)(W + seg * 64 * 64);
        #pragma unroll
        for (int i = 0; i < 4; ++i)
            ((float4*)sW)[tid + i * 256] = Wv[tid + i * 256];
        int lr = tid >> 4;
        int lc = (tid & 15) * 4;
        #pragma unroll
        for (int i = 0; i < 4; ++i) {
            int r = lr + i * 16;
            int gr = rowBase + r;
            float4 v = make_float4(0.f, 0.f, 0.f, 0.f);
            if (gr < n) v = *(const float4*)(A + (size_t)gr * 64 + lc);
            *(float4*)(&sA[r * 68 + lc]) = v;
        }
        __syncthreads();
        #pragma unroll
        for (int k = 0; k < 64; ++k) {
            float4 b = *(const float4*)(&sW[k * 64 + c0]);
            float a0 = sA[(r0 + 0) * 68 + k];
            float a1 = sA[(r0 + 1) * 68 + k];
            float a2 = sA[(r0 + 2) * 68 + k];
            float a3 = sA[(r0 + 3) * 68 + k];
            acc[0][0] += a0 * b.x; acc[0][1] += a0 * b.y; acc[0][2] += a0 * b.z; acc[0][3] += a0 * b.w;
            acc[1][0] += a1 * b.x; acc[1][1] += a1 * b.y; acc[1][2] += a1 * b.z; acc[1][3] += a1 * b.w;
            acc[2][0] += a2 * b.x; acc[2][1] += a2 * b.y; acc[2][2] += a2 * b.z; acc[2][3] += a2 * b.w;
            acc[3][0] += a3 * b.x; acc[3][1] += a3 * b.y; acc[3][2] += a3 * b.z; acc[3][3] += a3 * b.w;
        }
        __syncthreads();
    }

    float4 bv = make_float4(0.f, 0.f, 0.f, 0.f);
    if (bias) bv = *(const float4*)(bias + c0);
    #pragma unroll
    for (int i = 0; i < 4; ++i) {
        int gr = rowBase + r0 + i;
        if (gr < n) {
            float s = degscale ? degscale[gr] : 1.0f;
            float4 o;
            o.x = acc[i][0] + bv.x * s;
            o.y = acc[i][1] + bv.y * s;
            o.z = acc[i][2] + bv.z * s;
            o.w = acc[i][3] + bv.w * s;
            if (do_relu) {
                o.x = fmaxf(o.x, 0.f); o.y = fmaxf(o.y, 0.f);
                o.z = fmaxf(o.z, 0.f); o.w = fmaxf(o.w, 0.f);
            }
            *(float4*)(out + (size_t)gr * 64 + c0) = o;
        }
    }
}

// fused TAG + dual GEMM:
//   T = relu( x@W0 + h1@W1 + h2@W2 + h3@W3 + btag )   (kept in smem, not written)
//   out0 = T@Wa + ba,  out1 = T@Wb
__global__ void __launch_bounds__(256)
k_gemm_tag_dual(const float* A0, const float* A1, const float* A2, const float* A3,
                const float* __restrict__ Wtag, const float* __restrict__ btag,
                const float* __restrict__ Wa, const float* __restrict__ ba,
                const float* __restrict__ Wb,
                float* __restrict__ out0, float* __restrict__ out1, int n)
{
    __shared__ __align__(16) float sW[64 * 64];
    __shared__ __align__(16) float sA[64 * 68];
    const int tid = threadIdx.x;
    const int rowBase = blockIdx.x * 64;
    const int c0 = (tid & 15) * 4;
    const int r0 = (tid >> 4) * 4;
    const int lr = tid >> 4;
    const int lc = (tid & 15) * 4;
    const float* As[4] = {A0, A1, A2, A3};

    // phase 1: accumulate the 4 tag segments
    float acc[4][4] = {};
    for (int seg = 0; seg < 4; ++seg) {
        const float* A = As[seg];
        const float4* Wv = (const float4*)(Wtag + seg * 64 * 64);
        #pragma unroll
        for (int i = 0; i < 4; ++i)
            ((float4*)sW)[tid + i * 256] = Wv[tid + i * 256];
        #pragma unroll
        for (int i = 0; i < 4; ++i) {
            int r = lr + i * 16;
            int gr = rowBase + r;
            float4 v = make_float4(0.f, 0.f, 0.f, 0.f);
            if (gr < n) v = *(const float4*)(A + (size_t)gr * 64 + lc);
            *(float4*)(&sA[r * 68 + lc]) = v;
        }
        __syncthreads();
        #pragma unroll
        for (int k = 0; k < 64; ++k) {
            float4 b = *(const float4*)(&sW[k * 64 + c0]);
            float a0 = sA[(r0 + 0) * 68 + k];
            float a1 = sA[(r0 + 1) * 68 + k];
            float a2 = sA[(r0 + 2) * 68 + k];
            float a3 = sA[(r0 + 3) * 68 + k];
            acc[0][0] += a0 * b.x; acc[0][1] += a0 * b.y; acc[0][2] += a0 * b.z; acc[0][3] += a0 * b.w;
            acc[1][0] += a1 * b.x; acc[1][1] += a1 * b.y; acc[1][2] += a1 * b.z; acc[1][3] += a1 * b.w;
            acc[2][0] += a2 * b.x; acc[2][1] += a2 * b.y; acc[2][2] += a2 * b.z; acc[2][3] += a2 * b.w;
            acc[3][0] += a3 * b.x; acc[3][1] += a3 * b.y; acc[3][2] += a3 * b.z; acc[3][3] += a3 * b.w;
        }
        __syncthreads();
    }

    // bias + relu -> T, parked in sA (each thread owns rows r0..r0+3, cols c0..c0+3)
    {
        float4 bt = *(const float4*)(btag + c0);
        #pragma unroll
        for (int i = 0; i < 4; ++i) {
            float4 t;
            t.x = fmaxf(acc[i][0] + bt.x, 0.f);
            t.y = fmaxf(acc[i][1] + bt.y, 0.f);
            t.z = fmaxf(acc[i][2] + bt.z, 0.f);
            t.w = fmaxf(acc[i][3] + bt.w, 0.f);
            *(float4*)(&sA[(r0 + i) * 68 + c0]) = t;
        }
    }
    __syncthreads();

    // phase 2: dual GEMM from smem-resident T
    #pragma unroll
    for (int half = 0; half < 2; ++half) {
        const float4* Wv = (const float4*)(half ? Wb : Wa);
        #pragma unroll
        for (int i = 0; i < 4; ++i)
            ((float4*)sW)[tid + i * 256] = Wv[tid + i * 256];
        __syncthreads();
        float acc2[4][4] = {};
        #pragma unroll
        for (int k = 0; k < 64; ++k) {
            float4 b = *(const float4*)(&sW[k * 64 + c0]);
            float a0 = sA[(r0 + 0) * 68 + k];
            float a1 = sA[(r0 + 1) * 68 + k];
            float a2 = sA[(r0 + 2) * 68 + k];
            float a3 = sA[(r0 + 3) * 68 + k];
            acc2[0][0] += a0 * b.x; acc2[0][1] += a0 * b.y; acc2[0][2] += a0 * b.z; acc2[0][3] += a0 * b.w;
            acc2[1][0] += a1 * b.x; acc2[1][1] += a1 * b.y; acc2[1][2] += a1 * b.z; acc2[1][3] += a1 * b.w;
            acc2[2][0] += a2 * b.x; acc2[2][1] += a2 * b.y; acc2[2][2] += a2 * b.z; acc2[2][3] += a2 * b.w;
            acc2[3][0] += a3 * b.x; acc2[3][1] += a3 * b.y; acc2[3][2] += a3 * b.z; acc2[3][3] += a3 * b.w;
        }
        float4 bv = make_float4(0.f, 0.f, 0.f, 0.f);
        if (half == 0 && ba) bv = *(const float4*)(ba + c0);
        float* outp = half ? out1 : out0;
        #pragma unroll
        for (int i = 0; i < 4; ++i) {
            int gr = rowBase + r0 + i;
            if (gr < n) {
                float4 o;
                o.x = acc2[i][0] + bv.x; o.y = acc2[i][1] + bv.y;
                o.z = acc2[i][2] + bv.z; o.w = acc2[i][3] + bv.w;
                *(float4*)(outp + (size_t)gr * 64 + c0) = o;
            }
        }
        __syncthreads();
    }
}

// edge-body helper: acc(float4) = sum_e relu(xd + XS[src] + ea@W1e) for node wid,
// half-warp per edge, 8-edge main loop; result reduced across halves.
__device__ __forceinline__ float4
edge_body(int wid, int half, int hl, int c0,
          const float* __restrict__ XDb, const float* __restrict__ XS,
          const float* __restrict__ sE)
{
    float4 xd = *(const float4*)(XDb + (size_t)wid * 64 + c0);
    float4 w[5];
    #pragma unroll
    for (int k = 0; k < 5; ++k) w[k] = *(const float4*)(sE + k * 64 + c0);
    int e0 = g_ptr[wid], e1 = g_ptr[wid + 1];
    float4 acc = make_float4(0.f, 0.f, 0.f, 0.f);
    int e = e0;
    for (; e + 7 < e1; e += 8) {
        int s0 = g_src[e + half];
        int s1 = g_src[e + 2 + half];
        int s2 = g_src[e + 4 + half];
        int s3 = g_src[e + 6 + half];
        float q0 = (hl < 5) ? g_ea5[(size_t)(e + half) * 5 + hl] : 0.f;
        float q1 = (hl < 5) ? g_ea5[(size_t)(e + 2 + half) * 5 + hl] : 0.f;
        float q2 = (hl < 5) ? g_ea5[(size_t)(e + 4 + half) * 5 + hl] : 0.f;
        float q3 = (hl < 5) ? g_ea5[(size_t)(e + 6 + half) * 5 + hl] : 0.f;
        float4 v0 = *(const float4*)(XS + (size_t)s0 * 64 + c0);
        float4 v1 = *(const float4*)(XS + (size_t)s1 * 64 + c0);
        float4 v2 = *(const float4*)(XS + (size_t)s2 * 64 + c0);
        float4 v3 = *(const float4*)(XS + (size_t)s3 * 64 + c0);
        float p00 = xd.x + v0.x, p01 = xd.y + v0.y, p02 = xd.z + v0.z, p03 = xd.w + v0.w;
        float p10 = xd.x + v1.x, p11 = xd.y + v1.y, p12 = xd.z + v1.z, p13 = xd.w + v1.w;
        float p20 = xd.x + v2.x, p21 = xd.y + v2.y, p22 = xd.z + v2.z, p23 = xd.w + v2.w;
        float p30 = xd.x + v3.x, p31 = xd.y + v3.y, p32 = xd.z + v3.z, p33 = xd.w + v3.w;
        #pragma unroll
        for (int k = 0; k < 5; ++k) {
            float ek0 = __shfl_sync(0xffffffffu, q0, k, 16);
            float ek1 = __shfl_sync(0xffffffffu, q1, k, 16);
            float ek2 = __shfl_sync(0xffffffffu, q2, k, 16);
            float ek3 = __shfl_sync(0xffffffffu, q3, k, 16);
            p00 += ek0 * w[k].x; p01 += ek0 * w[k].y; p02 += ek0 * w[k].z; p03 += ek0 * w[k].w;
            p10 += ek1 * w[k].x; p11 += ek1 * w[k].y; p12 += ek1 * w[k].z; p13 += ek1 * w[k].w;
            p20 += ek2 * w[k].x; p21 += ek2 * w[k].y; p22 += ek2 * w[k].z; p23 += ek2 * w[k].w;
            p30 += ek3 * w[k].x; p31 += ek3 * w[k].y; p32 += ek3 * w[k].z; p33 += ek3 * w[k].w;
        }
        acc.x += fmaxf(p00, 0.f) + fmaxf(p10, 0.f) + fmaxf(p20, 0.f) + fmaxf(p30, 0.f);
        acc.y += fmaxf(p01, 0.f) + fmaxf(p11, 0.f) + fmaxf(p21, 0.f) + fmaxf(p31, 0.f);
        acc.z += fmaxf(p02, 0.f) + fmaxf(p12, 0.f) + fmaxf(p22, 0.f) + fmaxf(p32, 0.f);
        acc.w += fmaxf(p03, 0.f) + fmaxf(p13, 0.f) + fmaxf(p23, 0.f) + fmaxf(p33, 0.f);
    }
    for (; e + 1 < e1; e += 2) {
        int s = g_src[e + half];
        float q = (hl < 5) ? g_ea5[(size_t)(e + half) * 5 + hl] : 0.f;
        float4 v = *(const float4*)(XS + (size_t)s * 64 + c0);
        float p0 = xd.x + v.x, p1 = xd.y + v.y, p2 = xd.z + v.z, p3 = xd.w + v.w;
        #pragma unroll
        for (int k = 0; k < 5; ++k) {
            float ek = __shfl_sync(0xffffffffu, q, k, 16);
            p0 += ek * w[k].x; p1 += ek * w[k].y; p2 += ek * w[k].z; p3 += ek * w[k].w;
        }
        acc.x += fmaxf(p0, 0.f); acc.y += fmaxf(p1, 0.f);
        acc.z += fmaxf(p2, 0.f); acc.w += fmaxf(p3, 0.f);
    }
    if (e < e1) {
        int s = g_src[e];
        float q = (hl < 5) ? g_ea5[(size_t)e * 5 + hl] : 0.f;
        float4 v = *(const float4*)(XS + (size_t)s * 64 + c0);
        float p0 = xd.x + v.x, p1 = xd.y + v.y, p2 = xd.z + v.z, p3 = xd.w + v.w;
        #pragma unroll
        for (int k = 0; k < 5; ++k) {
            float ek = __shfl_sync(0xffffffffu, q, k, 16);
            p0 += ek * w[k].x; p1 += ek * w[k].y; p2 += ek * w[k].z; p3 += ek * w[k].w;
        }
        if (half == 0) {
            acc.x += fmaxf(p0, 0.f); acc.y += fmaxf(p1, 0.f);
            acc.z += fmaxf(p2, 0.f); acc.w += fmaxf(p3, 0.f);
        }
    }
    acc.x += __shfl_xor_sync(0xffffffffu, acc.x, 16);
    acc.y += __shfl_xor_sync(0xffffffffu, acc.y, 16);
    acc.z += __shfl_xor_sync(0xffffffffu, acc.z, 16);
    acc.w += __shfl_xor_sync(0xffffffffu, acc.w, 16);
    return acc;
}

// edge aggregation (mid layers): agg -> global
__global__ void __launch_bounds__(256)
k_edge(const float* __restrict__ XDb, const float* __restrict__ XS,
       const float* __restrict__ W1e, float* __restrict__ agg)
{
    __shared__ __align__(16) float sE[5 * 64];
    int tid = threadIdx.x;
    for (int i = tid; i < 5 * 64; i += 256) sE[i] = W1e[i];
    __syncthreads();
    int wid = (blockIdx.x * 256 + tid) >> 5;
    int lane = tid & 31;
    if (wid >= NN) return;
    int half = lane >> 4;
    int hl = lane & 15;
    int c0 = hl * 4;
    float4 acc = edge_body(wid, half, hl, c0, XDb, XS, sE);
    if (half == 0)
        *(float4*)(agg + (size_t)wid * 64 + c0) = acc;
}

// final-layer edge aggregation with fused 64x6 post-GEMV:
//   out[v][c] = agg[v]@W2[:,c] + deg[v]*b2[c]   (c in 0..5, no relu)
__global__ void __launch_bounds__(256)
k_edge_last(const float* __restrict__ XDb, const float* __restrict__ XS,
            const float* __restrict__ W1e, const float* __restrict__ W2,
            const float* __restrict__ b2, float* __restrict__ out)
{
    __shared__ __align__(16) float sRow[8][64];
    __shared__ __align__(16) float sE[5 * 64];
    __shared__ __align__(16) float sW2[64 * 6];
    __shared__ float sb2[6];
    int tid = threadIdx.x;
    for (int i = tid; i < 5 * 64; i += 256) sE[i] = W1e[i];
    for (int i = tid; i < 64 * 6; i += 256) sW2[i] = W2[i];
    if (tid < 6) sb2[tid] = b2[tid];
    __syncthreads();
    int wid = (blockIdx.x * 256 + tid) >> 5;
    int lane = tid & 31;
    int w = tid >> 5;
    if (wid >= NN) return;
    int half = lane >> 4;
    int hl = lane & 15;
    int c0 = hl * 4;
    float4 acc = edge_body(wid, half, hl, c0, XDb, XS, sE);
    if (half == 0)
        *(float4*)(&sRow[w][c0]) = acc;
    __syncwarp();
    if (lane < 6) {
        float dg = g_deg[wid];
        float a = dg * sb2[lane];
        #pragma unroll 8
        for (int k = 0; k < 64; ++k)
            a += sRow[w][k] * sW2[k * 6 + lane];
        out[(size_t)wid * 6 + lane] = a;
    }
}

// TAGConv propagation: Hn[v] = dis[v] * sum_e dis[src_e] * H[src_e]
// half-warp per edge, 16-edge main loop.
__global__ void __launch_bounds__(256)
k_prop(const float* __restrict__ H, float* __restrict__ Hn)
{
    int tid = threadIdx.x;
    int wid = (blockIdx.x * 256 + tid) >> 5;
    int lane = tid & 31;
    if (wid >= NN) return;
    int half = lane >> 4;
    int hl = lane & 15;
    int c0 = hl * 4;
    float dd = g_dis[wid];
    int e0 = g_ptr[wid], e1 = g_ptr[wid + 1];
    float4 acc = make_float4(0.f, 0.f, 0.f, 0.f);
    int e = e0;
    for (; e + 15 < e1; e += 16) {
        int s[8];
        #pragma unroll
        for (int i = 0; i < 8; ++i) s[i] = g_src[e + 2 * i + half];
        float nm[8];
        #pragma unroll
        for (int i = 0; i < 8; ++i) nm[i] = g_dis[s[i]];
        float4 v[8];
        #pragma unroll
        for (int i = 0; i < 8; ++i) v[i] = *(const float4*)(H + (size_t)s[i] * 64 + c0);
        #pragma unroll
        for (int i = 0; i < 8; ++i) {
            acc.x += nm[i] * v[i].x; acc.y += nm[i] * v[i].y;
            acc.z += nm[i] * v[i].z; acc.w += nm[i] * v[i].w;
        }
    }
    for (; e + 1 < e1; e += 2) {
        int s = g_src[e + half];
        float nr = g_dis[s];
        float4 v = *(const float4*)(H + (size_t)s * 64 + c0);
        acc.x += nr * v.x; acc.y += nr * v.y;
        acc.z += nr * v.z; acc.w += nr * v.w;
    }
    if (e < e1 && half == 0) {
        int s = g_src[e];
        float nr = g_dis[s];
        float4 v = *(const float4*)(H + (size_t)s * 64 + c0);
        acc.x += nr * v.x; acc.y += nr * v.y;
        acc.z += nr * v.z; acc.w += nr * v.w;
    }
    acc.x += __shfl_xor_sync(0xffffffffu, acc.x, 16);
    acc.y += __shfl_xor_sync(0xffffffffu, acc.y, 16);
    acc.z += __shfl_xor_sync(0xffffffffu, acc.z, 16);
    acc.w += __shfl_xor_sync(0xffffffffu, acc.w, 16);
    if (half == 0) {
        float4 o = make_float4(dd * acc.x, dd * acc.y, dd * acc.z, dd * acc.w);
        *(float4*)(Hn + (size_t)wid * 64 + c0) = o;
    }
}

// ---------------- host ----------------

extern "C" void kernel_launch(void* const* d_in, const int* in_sizes, int n_in,
                              void* d_out, int out_size)
{
    const float* data_x     = (const float*)d_in[0];
    const int*   edge_index = (const int*)  d_in[1];
    const float* edge_attr  = (const float*)d_in[2];
    const float* ea0_W1     = (const float*)d_in[3];
    const float* ea0_b1     = (const float*)d_in[4];
    const float* ea0_W2     = (const float*)d_in[5];
    const float* ea0_b2     = (const float*)d_in[6];
    const float* eam_W1     = (const float*)d_in[7];
    const float* eam_b1     = (const float*)d_in[8];
    const float* eam_W2     = (const float*)d_in[9];
    const float* eam_b2     = (const float*)d_in[10];
    const float* eal_W1     = (const float*)d_in[11];
    const float* eal_b1     = (const float*)d_in[12];
    const float* eal_W2     = (const float*)d_in[13];
    const float* eal_b2     = (const float*)d_in[14];
    const float* tag_W      = (const float*)d_in[15];
    const float* tag_b      = (const float*)d_in[16];
    float* out = (float*)d_out;

    float* pBuf = nullptr;
    float* pDeg = nullptr;
    int*   pCnt = nullptr;
    cudaGetSymbolAddress((void**)&pBuf, g_buf);
    cudaGetSymbolAddress((void**)&pDeg, g_deg);
    cudaGetSymbolAddress((void**)&pCnt, g_cnt);
    float* B0 = pBuf + 0 * (size_t)NN * HH;
    float* B1 = pBuf + 1 * (size_t)NN * HH;
    float* B2 = pBuf + 2 * (size_t)NN * HH;
    float* B3 = pBuf + 3 * (size_t)NN * HH;
    float* B4 = pBuf + 4 * (size_t)NN * HH;
    float* B5 = pBuf + 5 * (size_t)NN * HH;

    const int EB = (EE + 255) / 256;
    const int WB = (NN * 32 + 255) / 256;
    const int GB = (NN + 63) / 64;

    // CSR build
    cudaMemsetAsync(pCnt, 0, NN * sizeof(int));
    k_count<<<EB, 256>>>(edge_index);
    k_scan<<<1, 1024>>>();
    k_scatter<<<EB, 256>>>(edge_index, edge_attr);

    // layer 1: edge_agg ea0  (x = data_x[:,4:10])
    k_pre0<<<(NN * 128 + 255) / 256, 256>>>(data_x, ea0_W1, ea0_b1, B0, B1);
    k_edge<<<WB, 256>>>(B0, B1, ea0_W1 + 12 * 64, B2);
    k_gemm64<<<GB, 256>>>(B2, nullptr, nullptr, nullptr, 1, ea0_W2, ea0_b2, pDeg, B3, 1, NN);
    float* x = B3;

    for (int l = 0; l < 3; ++l) {
        const float* Wl = tag_W + (size_t)l * 4 * 64 * 64;
        const float* bl = tag_b + l * 64;
        // props: h1->B0, h2->B1, h3->B2
        k_prop<<<WB, 256>>>(x, B0);
        k_prop<<<WB, 256>>>(B0, B1);
        k_prop<<<WB, 256>>>(B1, B2);

        if (l < 2) {
            // fused: T = relu(tag) ; XDb = T@W1d + b1 -> B4 ; XS = T@W1s -> B5
            const float* W1 = eam_W1 + (size_t)l * 133 * 64;
            const float* b1 = eam_b1 + l * 64;
            const float* W2 = eam_W2 + (size_t)l * 64 * 64;
            const float* b2 = eam_b2 + l * 64;
            k_gemm_tag_dual<<<GB, 256>>>(x, B0, B1, B2, Wl, bl,
                                         W1, b1, W1 + 64 * 64, B4, B5, NN);
            k_edge<<<WB, 256>>>(B4, B5, W1 + 128 * 64, B2);
            k_gemm64<<<GB, 256>>>(B2, nullptr, nullptr, nullptr, 1, W2, b2, pDeg, B3, 1, NN);
            x = B3;
        } else {
            // final: fused tag + eal dual, then edge_last with 64x6 post
            k_gemm_tag_dual<<<GB, 256>>>(x, B0, B1, B2, Wl, bl,
                                         eal_W1, eal_b1, eal_W1 + 64 * 64, B4, B5, NN);
            k_edge_last<<<WB, 256>>>(B4, B5, eal_W1 + 128 * 64, eal_W2, eal_b2, out);
        }
    }
}